// round 1
// baseline (speedup 1.0000x reference)
#include <cuda_runtime.h>
#include <cstdint>
#include <cstdio>
#include <math.h>

// Problem constants
#define T_ 40
#define B_ 64
#define E_ 512
#define H_ 256          // encoder hidden per direction
#define DH_ 512         // decoder hidden (2H)
#define NL_ 2
#define VT_ 32000
#define TB_ (T_ * B_)

// ---------------- scratch (static device arrays; no allocation) ----------------
__device__ float g_X0[TB_ * E_];        // src embed / reused
__device__ float g_X1[TB_ * E_];        // enc layer0 output (concat) / dec L1 scratch
__device__ float g_D0[TB_ * E_];        // tgt embed / dec L1 output
__device__ float g_D1[TB_ * E_];        // dec L0 output
__device__ float g_xg_enc[TB_ * 2048];  // encoder gate inputs (both dirs)
__device__ float g_xg_dec[TB_ * 2048];  // decoder gate inputs
__device__ float g_henc[2 * 2 * B_ * H_];   // ping-pong x [dir][b][j]
__device__ float g_cenc[2 * B_ * H_];
__device__ float g_hdec[2 * B_ * DH_];      // ping-pong
__device__ float g_cdec[B_ * DH_];
__device__ float g_finh[NL_ * B_ * DH_];    // encoder finals, concat layout [b][d*H+j]
__device__ float g_finc[NL_ * B_ * DH_];

// ---------------- embedding gather ----------------
__global__ void embed_kernel(const int* __restrict__ idx,
                             const float* __restrict__ emb,
                             float* __restrict__ out) {
    int row = blockIdx.x;          // 0..TB_-1
    int e4  = threadIdx.x;         // 0..127 (E_/4)
    int id  = idx[row];
    float4 v = ((const float4*)(emb + (size_t)id * E_))[e4];
    ((float4*)(out + (size_t)row * E_))[e4] = v;
}

// ---------------- fp32 SGEMM: C[M,N] = A[M,K] @ W[N,K]^T + bias1 + bias2 ----------------
// All of M, N divisible by 128; K divisible by 16. No bounds checks.
#define BM 128
#define BN 128
#define BK 16
__global__ __launch_bounds__(256) void sgemm_nt(
    const float* __restrict__ A, const float* __restrict__ W,
    const float* __restrict__ bias1, const float* __restrict__ bias2,
    float* __restrict__ C, int M, int N, int K) {
    __shared__ float As[BK][BM];
    __shared__ float Ws[BK][BN];
    int bm = blockIdx.y * BM;
    int bn = blockIdx.x * BN;
    int tid = threadIdx.x;          // 0..255
    int ty = tid >> 4, tx = tid & 15;

    float acc[8][8];
#pragma unroll
    for (int i = 0; i < 8; i++)
#pragma unroll
        for (int j = 0; j < 8; j++) acc[i][j] = 0.0f;

    for (int k0 = 0; k0 < K; k0 += BK) {
#pragma unroll
        for (int i = 0; i < 2; i++) {
            int f = tid + i * 256;        // 0..511
            int row = f >> 2;             // 0..127
            int kq  = (f & 3) * 4;        // 0,4,8,12
            float4 va = *(const float4*)(A + (size_t)(bm + row) * K + k0 + kq);
            As[kq + 0][row] = va.x; As[kq + 1][row] = va.y;
            As[kq + 2][row] = va.z; As[kq + 3][row] = va.w;
            float4 vw = *(const float4*)(W + (size_t)(bn + row) * K + k0 + kq);
            Ws[kq + 0][row] = vw.x; Ws[kq + 1][row] = vw.y;
            Ws[kq + 2][row] = vw.z; Ws[kq + 3][row] = vw.w;
        }
        __syncthreads();
#pragma unroll
        for (int k = 0; k < BK; k++) {
            float a[8], b[8];
#pragma unroll
            for (int i = 0; i < 8; i++) a[i] = As[k][ty * 8 + i];
#pragma unroll
            for (int j = 0; j < 8; j++) b[j] = Ws[k][tx * 8 + j];
#pragma unroll
            for (int i = 0; i < 8; i++)
#pragma unroll
                for (int j = 0; j < 8; j++) acc[i][j] = fmaf(a[i], b[j], acc[i][j]);
        }
        __syncthreads();
    }

    float bb[8];
#pragma unroll
    for (int j = 0; j < 8; j++) {
        int col = bn + tx * 8 + j;
        float v = bias1 ? bias1[col] : 0.0f;
        if (bias2) v += bias2[col];
        bb[j] = v;
    }
#pragma unroll
    for (int i = 0; i < 8; i++) {
        size_t row = (size_t)(bm + ty * 8 + i);
        float* crow = C + row * (size_t)N + bn + tx * 8;
        float4 o0, o1;
        o0.x = acc[i][0] + bb[0]; o0.y = acc[i][1] + bb[1];
        o0.z = acc[i][2] + bb[2]; o0.w = acc[i][3] + bb[3];
        o1.x = acc[i][4] + bb[4]; o1.y = acc[i][5] + bb[5];
        o1.z = acc[i][6] + bb[6]; o1.w = acc[i][7] + bb[7];
        ((float4*)crow)[0] = o0;
        ((float4*)crow)[1] = o1;
    }
}

// ---------------- encoder LSTM step (both directions in one launch) ----------------
// grid = 128 CTAs x 256 thr; CTA 0..63 = fwd, 64..127 = bwd.
// thread -> (dir d, unit j, batch b). Gate order i,f,g,o. xg already holds bih+bhh.
__global__ __launch_bounds__(256) void enc_step_kernel(
    const float* __restrict__ xg,     // [T*B, 2048] (cols: d*1024 + g*256 + j)
    const float* __restrict__ Whh,    // layer base: [2][1024][256]
    const float* __restrict__ h_in,   // [2][B][H]
    float* __restrict__ h_out,        // [2][B][H]
    float* __restrict__ c_st,         // [2][B][H]
    float* __restrict__ y,            // [T*B, 512] or unused
    float* __restrict__ fin_h, float* __restrict__ fin_c, // [B*512]
    int t, int write_y) {
    extern __shared__ float hs[];     // [H][B] transposed
    int cta = blockIdx.x;
    int d = cta >> 6;
    int tid = threadIdx.x;
    const float* hsrc = h_in + d * (B_ * H_);
    for (int i = tid; i < B_ * H_; i += 256) {
        int bb = i >> 8;          // b
        int k  = i & 255;         // unit
        hs[k * B_ + bb] = hsrc[i];
    }
    __syncthreads();

    int j = (cta & 63) * 4 + (tid >> 6);
    int b = tid & 63;
    int time = d ? (T_ - 1 - t) : t;

    const float* xrow = xg + ((size_t)(time * B_ + b)) * 2048 + d * 1024;
    float gi = xrow[j], gf = xrow[256 + j], gg = xrow[512 + j], go = xrow[768 + j];

    const float4* Wi = (const float4*)(Whh + (size_t)(d * 1024 + 0   + j) * H_);
    const float4* Wf = (const float4*)(Whh + (size_t)(d * 1024 + 256 + j) * H_);
    const float4* Wg = (const float4*)(Whh + (size_t)(d * 1024 + 512 + j) * H_);
    const float4* Wo = (const float4*)(Whh + (size_t)(d * 1024 + 768 + j) * H_);

    float ai = 0.f, af = 0.f, ag = 0.f, ao = 0.f;
#pragma unroll 8
    for (int kq = 0; kq < H_ / 4; kq++) {
        float4 wi = Wi[kq], wf = Wf[kq], wg = Wg[kq], wo = Wo[kq];
        int k = kq * 4;
        float h0 = hs[(k + 0) * B_ + b];
        float h1 = hs[(k + 1) * B_ + b];
        float h2 = hs[(k + 2) * B_ + b];
        float h3 = hs[(k + 3) * B_ + b];
        ai = fmaf(wi.x, h0, fmaf(wi.y, h1, fmaf(wi.z, h2, fmaf(wi.w, h3, ai))));
        af = fmaf(wf.x, h0, fmaf(wf.y, h1, fmaf(wf.z, h2, fmaf(wf.w, h3, af))));
        ag = fmaf(wg.x, h0, fmaf(wg.y, h1, fmaf(wg.z, h2, fmaf(wg.w, h3, ag))));
        ao = fmaf(wo.x, h0, fmaf(wo.y, h1, fmaf(wo.z, h2, fmaf(wo.w, h3, ao))));
    }
    gi += ai; gf += af; gg += ag; go += ao;

    float si = 1.0f / (1.0f + expf(-gi));
    float sf = 1.0f / (1.0f + expf(-gf));
    float so = 1.0f / (1.0f + expf(-go));
    int ci = d * (B_ * H_) + b * H_ + j;
    float cn = sf * c_st[ci] + si * tanhf(gg);
    float hn = so * tanhf(cn);
    c_st[ci] = cn;
    h_out[ci] = hn;
    if (write_y) y[((size_t)(time * B_ + b)) * E_ + d * H_ + j] = hn;
    if (t == T_ - 1) {
        fin_h[b * DH_ + d * H_ + j] = hn;
        fin_c[b * DH_ + d * H_ + j] = cn;
    }
}

// ---------------- decoder LSTM step ----------------
// grid = 128 CTAs x 256 thr; thread -> (unit j in 0..511, batch b).
__global__ __launch_bounds__(256) void dec_step_kernel(
    const float* __restrict__ xg,     // [T*B, 2048] (cols: g*512 + j)
    const float* __restrict__ Whh,    // layer base [2048][512]
    const float* __restrict__ h_in,   // [B][512]
    float* __restrict__ h_out,
    float* __restrict__ c_st,         // [B][512]
    float* __restrict__ y,            // [T*B, 512]
    int t) {
    extern __shared__ float hs[];     // [512][B]
    int tid = threadIdx.x;
    for (int i = tid; i < B_ * DH_; i += 256) {
        int bb = i >> 9;
        int k  = i & 511;
        hs[k * B_ + bb] = h_in[i];
    }
    __syncthreads();

    int j = blockIdx.x * 4 + (tid >> 6);
    int b = tid & 63;

    const float* xrow = xg + ((size_t)(t * B_ + b)) * 2048;
    float gi = xrow[j], gf = xrow[512 + j], gg = xrow[1024 + j], go = xrow[1536 + j];

    const float4* Wi = (const float4*)(Whh + (size_t)(0    + j) * DH_);
    const float4* Wf = (const float4*)(Whh + (size_t)(512  + j) * DH_);
    const float4* Wg = (const float4*)(Whh + (size_t)(1024 + j) * DH_);
    const float4* Wo = (const float4*)(Whh + (size_t)(1536 + j) * DH_);

    float ai = 0.f, af = 0.f, ag = 0.f, ao = 0.f;
#pragma unroll 8
    for (int kq = 0; kq < DH_ / 4; kq++) {
        float4 wi = Wi[kq], wf = Wf[kq], wg = Wg[kq], wo = Wo[kq];
        int k = kq * 4;
        float h0 = hs[(k + 0) * B_ + b];
        float h1 = hs[(k + 1) * B_ + b];
        float h2 = hs[(k + 2) * B_ + b];
        float h3 = hs[(k + 3) * B_ + b];
        ai = fmaf(wi.x, h0, fmaf(wi.y, h1, fmaf(wi.z, h2, fmaf(wi.w, h3, ai))));
        af = fmaf(wf.x, h0, fmaf(wf.y, h1, fmaf(wf.z, h2, fmaf(wf.w, h3, af))));
        ag = fmaf(wg.x, h0, fmaf(wg.y, h1, fmaf(wg.z, h2, fmaf(wg.w, h3, ag))));
        ao = fmaf(wo.x, h0, fmaf(wo.y, h1, fmaf(wo.z, h2, fmaf(wo.w, h3, ao))));
    }
    gi += ai; gf += af; gg += ag; go += ao;

    float si = 1.0f / (1.0f + expf(-gi));
    float sf = 1.0f / (1.0f + expf(-gf));
    float so = 1.0f / (1.0f + expf(-go));
    int ci = b * DH_ + j;
    float cn = sf * c_st[ci] + si * tanhf(gg);
    float hn = so * tanhf(cn);
    c_st[ci] = cn;
    h_out[ci] = hn;
    y[((size_t)(t * B_ + b)) * E_ + j] = hn;
}

// ---------------- host launch ----------------
extern "C" void kernel_launch(void* const* d_in, const int* in_sizes, int n_in,
                              void* d_out, int out_size) {
    const int*   src     = (const int*)d_in[0];
    const int*   tgt     = (const int*)d_in[1];
    const float* src_emb = (const float*)d_in[2];
    const float* tgt_emb = (const float*)d_in[3];
    const float* enc_Wih = (const float*)d_in[4];   // [2,2,1024,512]
    const float* enc_Whh = (const float*)d_in[5];   // [2,2,1024,256]
    const float* enc_bih = (const float*)d_in[6];   // [2,2048]
    const float* enc_bhh = (const float*)d_in[7];
    const float* dec_Wih = (const float*)d_in[8];   // [2,2048,512]
    const float* dec_Whh = (const float*)d_in[9];   // [2,2048,512]
    const float* dec_bih = (const float*)d_in[10];  // [2,2048]
    const float* dec_bhh = (const float*)d_in[11];
    const float* lin_W   = (const float*)d_in[12];  // [32000,512]
    const float* lin_b   = (const float*)d_in[13];
    float* out = (float*)d_out;

    float *X0, *X1, *D0, *D1, *XGE, *XGD, *HE, *CE, *HD, *CD, *FH, *FC;
    cudaGetSymbolAddress((void**)&X0,  g_X0);
    cudaGetSymbolAddress((void**)&X1,  g_X1);
    cudaGetSymbolAddress((void**)&D0,  g_D0);
    cudaGetSymbolAddress((void**)&D1,  g_D1);
    cudaGetSymbolAddress((void**)&XGE, g_xg_enc);
    cudaGetSymbolAddress((void**)&XGD, g_xg_dec);
    cudaGetSymbolAddress((void**)&HE,  g_henc);
    cudaGetSymbolAddress((void**)&CE,  g_cenc);
    cudaGetSymbolAddress((void**)&HD,  g_hdec);
    cudaGetSymbolAddress((void**)&CD,  g_cdec);
    cudaGetSymbolAddress((void**)&FH,  g_finh);
    cudaGetSymbolAddress((void**)&FC,  g_finc);

    cudaFuncSetAttribute(enc_step_kernel, cudaFuncAttributeMaxDynamicSharedMemorySize, B_ * H_ * 4);
    cudaFuncSetAttribute(dec_step_kernel, cudaFuncAttributeMaxDynamicSharedMemorySize, B_ * DH_ * 4);

    const int enc_smem = B_ * H_ * 4;    // 64 KB
    const int dec_smem = B_ * DH_ * 4;   // 128 KB

    // embeddings
    embed_kernel<<<TB_, 128>>>(src, src_emb, X0);
    embed_kernel<<<TB_, 128>>>(tgt, tgt_emb, D0);

    dim3 blk(256);
    dim3 grid_xg(2048 / BN, TB_ / BM);     // (16, 20)
    dim3 grid_pj(VT_ / BN, TB_ / BM);      // (250, 20)

    // ---- encoder ----
    const float* xin[2] = {X0, X1};
    for (int l = 0; l < NL_; l++) {
        sgemm_nt<<<grid_xg, blk>>>(xin[l], enc_Wih + (size_t)l * 2048 * E_,
                                   enc_bih + l * 2048, enc_bhh + l * 2048,
                                   XGE, TB_, 2048, E_);
        cudaMemsetAsync(HE, 0, 2 * 2 * B_ * H_ * sizeof(float), 0);
        cudaMemsetAsync(CE, 0, 2 * B_ * H_ * sizeof(float), 0);
        const float* Whh_l = enc_Whh + (size_t)l * 2 * 1024 * H_;
        for (int t = 0; t < T_; t++) {
            float* h_in  = HE + (t & 1) * (2 * B_ * H_);
            float* h_out = HE + ((t + 1) & 1) * (2 * B_ * H_);
            enc_step_kernel<<<128, 256, enc_smem>>>(
                XGE, Whh_l, h_in, h_out, CE,
                X1, FH + l * B_ * DH_, FC + l * B_ * DH_,
                t, (l == 0) ? 1 : 0);
        }
    }

    // ---- decoder ----
    const float* din[2]  = {D0, D1};
    float*       dout[2] = {D1, X1};   // X1 free after encoder layer-1 xg GEMM
    for (int l = 0; l < NL_; l++) {
        sgemm_nt<<<grid_xg, blk>>>(din[l], dec_Wih + (size_t)l * 2048 * E_,
                                   dec_bih + l * 2048, dec_bhh + l * 2048,
                                   XGD, TB_, 2048, E_);
        cudaMemcpyAsync(HD, FH + l * B_ * DH_, B_ * DH_ * sizeof(float),
                        cudaMemcpyDeviceToDevice, 0);
        cudaMemcpyAsync(CD, FC + l * B_ * DH_, B_ * DH_ * sizeof(float),
                        cudaMemcpyDeviceToDevice, 0);
        const float* Whh_l = dec_Whh + (size_t)l * 2048 * DH_;
        for (int t = 0; t < T_; t++) {
            float* h_in  = HD + (t & 1) * (B_ * DH_);
            float* h_out = HD + ((t + 1) & 1) * (B_ * DH_);
            dec_step_kernel<<<128, 256, dec_smem>>>(
                XGD, Whh_l, h_in, h_out, CD, dout[l], t);
        }
    }

    // ---- output projection ----
    sgemm_nt<<<grid_pj, blk>>>(X1, lin_W, lin_b, nullptr, out, TB_, VT_, E_);
}